// round 4
// baseline (speedup 1.0000x reference)
#include <cuda_runtime.h>

#define N_NODES 50000
#define N_EDGES 800000
#define D 64
#define D4 (D / 4)          // 16 float4 per node row
#define NCLS 16

// ---------------- scratch (no allocation allowed; float4 => 16B aligned) ----------------
__device__ float  g_deg[N_NODES];
__device__ float  g_dinv[N_NODES];
__device__ float4 g_h4[N_NODES * D4];    // GEMM output per layer
__device__ float4 g_agg4[N_NODES * D4];  // aggregation buffer per layer

// ---------------- degree / norm ----------------
__global__ void deg_init_kernel(float* deg) {
    int i = blockIdx.x * blockDim.x + threadIdx.x;
    if (i < N_NODES) deg[i] = 1.0f;  // self-loop weight
}

__global__ void deg_edges_kernel(const int* __restrict__ ei,
                                 const float* __restrict__ ew,
                                 float* deg) {
    int e = blockIdx.x * blockDim.x + threadIdx.x;
    if (e < N_EDGES) {
        int c = ei[N_EDGES + e];
        atomicAdd(&deg[c], ew[e]);
    }
}

__global__ void dinv_kernel(const float* __restrict__ deg, float* dinv) {
    int i = blockIdx.x * blockDim.x + threadIdx.x;
    if (i < N_NODES) dinv[i] = rsqrtf(deg[i]);  // deg >= 1 always (self loop)
}

// ---------------- 64x64 GEMM: H = (relu?)(X) @ W ----------------
// block = (64, 4) threads; 32 rows per tile, grid-stride over row tiles.
template <bool RELU_IN>
__global__ void gemm64_kernel(const float* __restrict__ X,
                              const float* __restrict__ W,
                              float* __restrict__ H) {
    __shared__ float Ws[64][64];
    __shared__ float Xs[32][64];
    const int tx = threadIdx.x;          // 0..63 (output col)
    const int ty = threadIdx.y;          // 0..3
    const int tid = ty * 64 + tx;

    for (int i = tid; i < 64 * 64; i += 256)
        Ws[i >> 6][i & 63] = W[i];
    __syncthreads();

    for (int rb = blockIdx.x * 32; rb < N_NODES; rb += gridDim.x * 32) {
        const int rows = min(32, N_NODES - rb);
        // stage X rows
        for (int i = tid; i < rows * 64; i += 256) {
            float v = X[rb * 64 + i];
            if (RELU_IN) v = fmaxf(v, 0.0f);
            Xs[i >> 6][i & 63] = v;
        }
        __syncthreads();

        #pragma unroll
        for (int j = 0; j < 8; j++) {
            const int r = ty + j * 4;
            if (r < rows) {
                float acc = 0.0f;
                #pragma unroll
                for (int k = 0; k < 64; k++)
                    acc = fmaf(Xs[r][k], Ws[k][tx], acc);
                H[(rb + r) * 64 + tx] = acc;
            }
        }
        __syncthreads();
    }
}

// ---------------- agg init: self-loop + bias (vectorized) ----------------
__global__ void agg_init_kernel(const float4* __restrict__ h4,
                                const float* __restrict__ dinv,
                                const float* __restrict__ b,   // harness ptr, 256B aligned
                                float4* __restrict__ agg4) {
    int i = blockIdx.x * blockDim.x + threadIdx.x;
    if (i < N_NODES * D4) {
        int node = i >> 4;           // /16
        int f4   = i & 15;
        float di = dinv[node];
        float d2 = di * di;
        float4 hv = h4[i];
        float4 bv = reinterpret_cast<const float4*>(b)[f4];
        agg4[i] = make_float4(fmaf(d2, hv.x, bv.x), fmaf(d2, hv.y, bv.y),
                              fmaf(d2, hv.z, bv.z), fmaf(d2, hv.w, bv.w));
    }
}

// ---------------- edge scatter: agg[col] += norm * h[row] ----------------
// 16 threads per edge, each handles one float4 via red.global.add.v4.f32
__global__ void scatter_kernel(const int* __restrict__ ei,
                               const float* __restrict__ ew,
                               const float* __restrict__ dinv,
                               const float4* __restrict__ h4,
                               float4* __restrict__ agg4) {
    int t = blockIdx.x * blockDim.x + threadIdx.x;
    int e = t >> 4;
    if (e >= N_EDGES) return;
    int sub = t & 15;

    int r = ei[e];
    int c = ei[N_EDGES + e];
    float norm = dinv[r] * ew[e] * dinv[c];

    float4 hv = h4[r * D4 + sub];
    float4* dst = agg4 + c * D4 + sub;
    asm volatile("red.global.add.v4.f32 [%0], {%1, %2, %3, %4};"
                 :: "l"(dst),
                    "f"(norm * hv.x), "f"(norm * hv.y),
                    "f"(norm * hv.z), "f"(norm * hv.w)
                 : "memory");
}

// ---------------- fused MLP head + sigmoid ----------------
// block = (64, 4): 4 rows per iter, grid-stride.
__global__ void mlp_kernel(const float* __restrict__ A,
                           const float* __restrict__ Wm1,
                           const float* __restrict__ bm1,
                           const float* __restrict__ Wm2,
                           const float* __restrict__ bm2,
                           float* __restrict__ out) {
    __shared__ float W1s[64][64];
    __shared__ float W2s[64][NCLS];
    __shared__ float b1s[64];
    __shared__ float b2s[NCLS];
    __shared__ float T[4][64];

    const int tx = threadIdx.x;
    const int ty = threadIdx.y;
    const int tid = ty * 64 + tx;

    for (int i = tid; i < 64 * 64; i += 256)
        W1s[i >> 6][i & 63] = Wm1[i];
    for (int i = tid; i < 64 * NCLS; i += 256)
        W2s[i / NCLS][i % NCLS] = Wm2[i];
    if (tid < 64) b1s[tid] = bm1[tid];
    if (tid < NCLS) b2s[tid] = bm2[tid];
    __syncthreads();

    for (int r0 = blockIdx.x * 4; r0 < N_NODES; r0 += gridDim.x * 4) {
        const int r = r0 + ty;
        float acc = b1s[tx];
        if (r < N_NODES) {
            const float* a = A + (long long)r * 64;
            #pragma unroll
            for (int k = 0; k < 64; k++)
                acc = fmaf(fmaxf(a[k], 0.0f), W1s[k][tx], acc);
        }
        T[ty][tx] = fmaxf(acc, 0.0f);
        __syncthreads();

        if (tx < NCLS && r < N_NODES) {
            float acc2 = b2s[tx];
            #pragma unroll
            for (int k = 0; k < 64; k++)
                acc2 = fmaf(T[ty][k], W2s[k][tx], acc2);
            out[(long long)r * NCLS + tx] = 1.0f / (1.0f + __expf(-acc2));
        }
        __syncthreads();
    }
}

// ---------------- launch ----------------
extern "C" void kernel_launch(void* const* d_in, const int* in_sizes, int n_in,
                              void* d_out, int out_size) {
    const float* x    = (const float*)d_in[0];
    const int*   ei   = (const int*)d_in[1];      // int32 (harness downcasts int64)
    const float* ew   = (const float*)d_in[2];
    const float* W1   = (const float*)d_in[3];
    const float* b1   = (const float*)d_in[4];
    const float* W2   = (const float*)d_in[5];
    const float* b2   = (const float*)d_in[6];
    const float* Wm1  = (const float*)d_in[7];
    const float* bm1  = (const float*)d_in[8];
    const float* Wm2  = (const float*)d_in[9];
    const float* bm2  = (const float*)d_in[10];
    float* out = (float*)d_out;

    float  *p_deg, *p_dinv;
    float4 *p_h4, *p_agg4;
    cudaGetSymbolAddress((void**)&p_deg,  g_deg);
    cudaGetSymbolAddress((void**)&p_dinv, g_dinv);
    cudaGetSymbolAddress((void**)&p_h4,   g_h4);
    cudaGetSymbolAddress((void**)&p_agg4, g_agg4);
    float* p_h   = (float*)p_h4;
    float* p_agg = (float*)p_agg4;

    const dim3 blk2d(64, 4);
    const int GEMM_GRID = 592;   // 148 SMs * 4
    const int MLP_GRID  = 1184;

    // norms
    deg_init_kernel<<<(N_NODES + 255) / 256, 256>>>(p_deg);
    deg_edges_kernel<<<(N_EDGES + 255) / 256, 256>>>(ei, ew, p_deg);
    dinv_kernel<<<(N_NODES + 255) / 256, 256>>>(p_deg, p_dinv);

    // layer 1
    gemm64_kernel<false><<<GEMM_GRID, blk2d>>>(x, W1, p_h);
    agg_init_kernel<<<(N_NODES * D4 + 255) / 256, 256>>>(p_h4, p_dinv, b1, p_agg4);
    scatter_kernel<<<(N_EDGES * 16 + 255) / 256, 256>>>(ei, ew, p_dinv, p_h4, p_agg4);

    // layer 2 (relu on layer-1 output fused into GEMM input load)
    gemm64_kernel<true><<<GEMM_GRID, blk2d>>>(p_agg, W2, p_h);
    agg_init_kernel<<<(N_NODES * D4 + 255) / 256, 256>>>(p_h4, p_dinv, b2, p_agg4);
    scatter_kernel<<<(N_EDGES * 16 + 255) / 256, 256>>>(ei, ew, p_dinv, p_h4, p_agg4);

    // MLP head (relu on layer-2 output fused into load) + sigmoid
    mlp_kernel<<<MLP_GRID, blk2d>>>(p_agg, Wm1, bm1, Wm2, bm2, out);
}

// round 5
// speedup vs baseline: 1.4946x; 1.4946x over previous
#include <cuda_runtime.h>

#define N_NODES 50000
#define N_EDGES 800000
#define D 64
#define D4 (D / 4)
#define NCLS 16
#define ROW_TILES ((N_NODES + 63) / 64)   // 782

// ---------------- scratch (float4 => 16B aligned) ----------------
__device__ float  g_deg[N_NODES];
__device__ float  g_dinv[N_NODES];
__device__ float  g_norm[N_EDGES];
__device__ float4 g_h4[N_NODES * D4];    // GEMM output per layer
__device__ float4 g_agg4[N_NODES * D4];  // aggregation buffer per layer

// ---------------- degree / norm ----------------
__global__ void deg_init_kernel(float* deg) {
    int i = blockIdx.x * blockDim.x + threadIdx.x;
    if (i < N_NODES) deg[i] = 1.0f;  // self-loop weight
}

__global__ void deg_edges_kernel(const int* __restrict__ ei,
                                 const float* __restrict__ ew,
                                 float* deg) {
    int e = blockIdx.x * blockDim.x + threadIdx.x;
    if (e < N_EDGES) atomicAdd(&deg[ei[N_EDGES + e]], ew[e]);
}

__global__ void dinv_kernel(const float* __restrict__ deg, float* dinv) {
    int i = blockIdx.x * blockDim.x + threadIdx.x;
    if (i < N_NODES) dinv[i] = rsqrtf(deg[i]);
}

__global__ void norm_kernel(const int* __restrict__ ei,
                            const float* __restrict__ ew,
                            const float* __restrict__ dinv,
                            float* __restrict__ norm) {
    int e = blockIdx.x * blockDim.x + threadIdx.x;
    if (e < N_EDGES) {
        int r = ei[e];
        int c = ei[N_EDGES + e];
        norm[e] = dinv[r] * ew[e] * dinv[c];
    }
}

// ---------------- register-blocked 64x64 GEMM + fused agg init ----------------
// block (64,4); 64 rows per block; thread tx owns column tx for 16 rows.
// Writes h = X@W and agg = dinv^2 * h + b in one pass.
// Safe in-place when X == agg: each row tile is staged to smem by the only
// block that writes it, with a __syncthreads between.
template <bool RELU_IN>
__global__ void gemm64_fused_kernel(const float* __restrict__ X,
                                    const float* __restrict__ W,
                                    const float* __restrict__ dinv,
                                    const float* __restrict__ b,
                                    float* __restrict__ H,
                                    float* __restrict__ AGG) {
    __shared__ float Ws[64][64];
    __shared__ float Xs[64][64];
    const int tx = threadIdx.x;
    const int ty = threadIdx.y;
    const int tid = ty * 64 + tx;
    const int rb = blockIdx.x * 64;
    const int rows = min(64, N_NODES - rb);

    for (int i = tid; i < 64 * 64; i += 256)
        Ws[i >> 6][i & 63] = W[i];
    for (int i = tid; i < rows * 64; i += 256) {
        float v = X[rb * 64 + i];
        if (RELU_IN) v = fmaxf(v, 0.0f);
        Xs[i >> 6][i & 63] = v;
    }
    __syncthreads();

    float acc[16];
    #pragma unroll
    for (int j = 0; j < 16; j++) acc[j] = 0.0f;

    #pragma unroll
    for (int k0 = 0; k0 < 64; k0 += 4) {
        const float w0 = Ws[k0 + 0][tx];
        const float w1 = Ws[k0 + 1][tx];
        const float w2 = Ws[k0 + 2][tx];
        const float w3 = Ws[k0 + 3][tx];
        #pragma unroll
        for (int j = 0; j < 16; j++) {
            const int r = (j << 2) + ty;
            float4 xv = *reinterpret_cast<const float4*>(&Xs[r][k0]);
            acc[j] = fmaf(xv.x, w0, fmaf(xv.y, w1, fmaf(xv.z, w2, fmaf(xv.w, w3, acc[j]))));
        }
    }

    const float bv = b[tx];
    #pragma unroll
    for (int j = 0; j < 16; j++) {
        const int r = (j << 2) + ty;
        const int gr = rb + r;
        if (gr < N_NODES) {
            const float a = acc[j];
            H[gr * 64 + tx] = a;
            const float di = dinv[gr];
            AGG[gr * 64 + tx] = fmaf(di * di, a, bv);
        }
    }
}

// ---------------- edge scatter: agg[col] += norm * h[row] ----------------
// 16 threads per edge, one float4 each via red.global.add.v4.f32
__global__ void scatter_kernel(const int* __restrict__ ei,
                               const float* __restrict__ norm,
                               const float4* __restrict__ h4,
                               float4* __restrict__ agg4) {
    int t = blockIdx.x * blockDim.x + threadIdx.x;
    int e = t >> 4;
    if (e >= N_EDGES) return;
    int sub = t & 15;

    int r = ei[e];
    int c = ei[N_EDGES + e];
    float nm = norm[e];

    float4 hv = h4[r * D4 + sub];
    float4* dst = agg4 + c * D4 + sub;
    asm volatile("red.global.add.v4.f32 [%0], {%1, %2, %3, %4};"
                 :: "l"(dst),
                    "f"(nm * hv.x), "f"(nm * hv.y),
                    "f"(nm * hv.z), "f"(nm * hv.w)
                 : "memory");
}

// ---------------- fused MLP head + sigmoid ----------------
// block (64,4); 64 rows per block. Stage1 register-blocked like the GEMM,
// stage2 uses all 256 threads (16 rows x 16 classes, 4 row-groups).
__global__ void mlp_kernel(const float* __restrict__ A,
                           const float* __restrict__ Wm1,
                           const float* __restrict__ bm1,
                           const float* __restrict__ Wm2,
                           const float* __restrict__ bm2,
                           float* __restrict__ out) {
    __shared__ float W1s[64][64];
    __shared__ float Xs[64][64];
    __shared__ float T[64][68];     // padded: rows 68 apart -> conflict-free stage2
    __shared__ float W2s[64][NCLS];
    __shared__ float b1s[64];
    __shared__ float b2s[NCLS];

    const int tx = threadIdx.x;
    const int ty = threadIdx.y;
    const int tid = ty * 64 + tx;
    const int rb = blockIdx.x * 64;
    const int rows = min(64, N_NODES - rb);

    for (int i = tid; i < 64 * 64; i += 256)
        W1s[i >> 6][i & 63] = Wm1[i];
    for (int i = tid; i < 64 * NCLS; i += 256)
        W2s[i / NCLS][i % NCLS] = Wm2[i];
    if (tid < 64) b1s[tid] = bm1[tid];
    if (tid < NCLS) b2s[tid] = bm2[tid];
    for (int i = tid; i < rows * 64; i += 256)
        Xs[i >> 6][i & 63] = fmaxf(A[rb * 64 + i], 0.0f);   // relu on GCN output
    __syncthreads();

    // stage 1: T = relu(relu(A) @ Wm1 + bm1)
    float acc[16];
    #pragma unroll
    for (int j = 0; j < 16; j++) acc[j] = b1s[tx];

    #pragma unroll
    for (int k0 = 0; k0 < 64; k0 += 4) {
        const float w0 = W1s[k0 + 0][tx];
        const float w1 = W1s[k0 + 1][tx];
        const float w2 = W1s[k0 + 2][tx];
        const float w3 = W1s[k0 + 3][tx];
        #pragma unroll
        for (int j = 0; j < 16; j++) {
            const int r = (j << 2) + ty;
            float4 xv = *reinterpret_cast<const float4*>(&Xs[r][k0]);
            acc[j] = fmaf(xv.x, w0, fmaf(xv.y, w1, fmaf(xv.z, w2, fmaf(xv.w, w3, acc[j]))));
        }
    }
    #pragma unroll
    for (int j = 0; j < 16; j++)
        T[(j << 2) + ty][tx] = fmaxf(acc[j], 0.0f);
    __syncthreads();

    // stage 2: out = sigmoid(T @ Wm2 + bm2); 256 threads = 16 rows x 16 cls
    const int row16 = tid >> 4;   // 0..15
    const int cls   = tid & 15;
    #pragma unroll
    for (int rr = 0; rr < 4; rr++) {
        const int row = rr * 16 + row16;
        const int gr = rb + row;
        float acc2 = b2s[cls];
        #pragma unroll
        for (int k = 0; k < 64; k++)
            acc2 = fmaf(T[row][k], W2s[k][cls], acc2);
        if (gr < N_NODES)
            out[gr * NCLS + cls] = 1.0f / (1.0f + __expf(-acc2));
    }
}

// ---------------- launch ----------------
extern "C" void kernel_launch(void* const* d_in, const int* in_sizes, int n_in,
                              void* d_out, int out_size) {
    const float* x    = (const float*)d_in[0];
    const int*   ei   = (const int*)d_in[1];
    const float* ew   = (const float*)d_in[2];
    const float* W1   = (const float*)d_in[3];
    const float* b1   = (const float*)d_in[4];
    const float* W2   = (const float*)d_in[5];
    const float* b2   = (const float*)d_in[6];
    const float* Wm1  = (const float*)d_in[7];
    const float* bm1  = (const float*)d_in[8];
    const float* Wm2  = (const float*)d_in[9];
    const float* bm2  = (const float*)d_in[10];
    float* out = (float*)d_out;

    float  *p_deg, *p_dinv, *p_norm;
    float4 *p_h4, *p_agg4;
    cudaGetSymbolAddress((void**)&p_deg,  g_deg);
    cudaGetSymbolAddress((void**)&p_dinv, g_dinv);
    cudaGetSymbolAddress((void**)&p_norm, g_norm);
    cudaGetSymbolAddress((void**)&p_h4,   g_h4);
    cudaGetSymbolAddress((void**)&p_agg4, g_agg4);
    float* p_h   = (float*)p_h4;
    float* p_agg = (float*)p_agg4;

    const dim3 blk2d(64, 4);

    // norms (graph-invariant: computed once per launch, reused by both layers)
    deg_init_kernel<<<(N_NODES + 255) / 256, 256>>>(p_deg);
    deg_edges_kernel<<<(N_EDGES + 255) / 256, 256>>>(ei, ew, p_deg);
    dinv_kernel<<<(N_NODES + 255) / 256, 256>>>(p_deg, p_dinv);
    norm_kernel<<<(N_EDGES + 255) / 256, 256>>>(ei, ew, p_dinv, p_norm);

    // layer 1: h = x@W1; agg = dinv^2*h + b1; scatter edges
    gemm64_fused_kernel<false><<<ROW_TILES, blk2d>>>(x, W1, p_dinv, b1, p_h, p_agg);
    scatter_kernel<<<(N_EDGES * 16 + 255) / 256, 256>>>(ei, p_norm, p_h4, p_agg4);

    // layer 2: in-place relu(agg)@W2 -> h, agg re-init; scatter
    gemm64_fused_kernel<true><<<ROW_TILES, blk2d>>>(p_agg, W2, p_dinv, b2, p_h, p_agg);
    scatter_kernel<<<(N_EDGES * 16 + 255) / 256, 256>>>(ei, p_norm, p_h4, p_agg4);

    // MLP head + sigmoid
    mlp_kernel<<<ROW_TILES, blk2d>>>(p_agg, Wm1, bm1, Wm2, bm2, out);
}